// round 1
// baseline (speedup 1.0000x reference)
#include <cuda_runtime.h>
#include <math_constants.h>

// Problem constants
#define BB 4
#define SS 4096
#define EE 256
#define DD 32

// Scratch for projected Q/K/V: [B, S, D] fp32 each (2 MB each; static, allocation-guard safe)
__device__ float g_q[BB * SS * DD];
__device__ float g_k[BB * SS * DD];
__device__ float g_v[BB * SS * DD];

// ---------------------------------------------------------------------------
// Projection kernel: q/k/v = x @ W{q,k,v}.  One block = 32 rows of x.
// 256 threads: thread (rg, col) computes 4 rows x 1 col for all three mats.
// ---------------------------------------------------------------------------
__global__ __launch_bounds__(256, 1) void proj_kernel(
    const float* __restrict__ x,
    const float* __restrict__ Wq,
    const float* __restrict__ Wk,
    const float* __restrict__ Wv)
{
    __shared__ float xs[32 * EE];  // 32 KB
    const int row0 = blockIdx.x * 32;
    const int tid = threadIdx.x;

    // Cooperative load of x tile (32x256 fp32) as float4, fully coalesced.
    const float4* xg = (const float4*)(x + (size_t)row0 * EE);
    float4* xs4 = (float4*)xs;
#pragma unroll
    for (int i = 0; i < 8; i++) xs4[tid + i * 256] = xg[tid + i * 256];
    __syncthreads();

    const int col = tid & 31;   // output dim
    const int rg  = tid >> 5;   // row group (4 rows each)

    float aq[4] = {0.f, 0.f, 0.f, 0.f};
    float ak[4] = {0.f, 0.f, 0.f, 0.f};
    float av[4] = {0.f, 0.f, 0.f, 0.f};

#pragma unroll 4
    for (int e = 0; e < EE; e++) {
        const float wq = __ldg(&Wq[e * DD + col]);  // coalesced, L1-resident (32 KB each)
        const float wk = __ldg(&Wk[e * DD + col]);
        const float wv = __ldg(&Wv[e * DD + col]);
#pragma unroll
        for (int rr = 0; rr < 4; rr++) {
            const float xv = xs[(rg * 4 + rr) * EE + e];  // broadcast within warp
            aq[rr] += xv * wq;
            ak[rr] += xv * wk;
            av[rr] += xv * wv;
        }
    }

#pragma unroll
    for (int rr = 0; rr < 4; rr++) {
        const int r = row0 + rg * 4 + rr;
        g_q[r * DD + col] = aq[rr];
        g_k[r * DD + col] = ak[rr];
        g_v[r * DD + col] = av[rr];
    }
}

// ---------------------------------------------------------------------------
// Flash-style attention (fp32, online softmax, post-softmax scaling).
// Block: 256 threads = 32 queries x 8 threads/query. Key chunks of 64.
// SMEM row stride 36 floats: float4-aligned AND bank-conflict-free
// (bank group of row j for lane sub: 4*sub mod 32 distinct for sub in [0,8)).
// ---------------------------------------------------------------------------
#define BQ 32
#define BK 64
#define KST 36   // q/k/v smem row stride (floats)
#define PST 65   // p smem row stride (floats)

__global__ __launch_bounds__(256, 1) void attn_kernel(float* __restrict__ out)
{
    __shared__ float qs[BQ * KST];   // 4.6 KB
    __shared__ float ks[BK * KST];   // 9.2 KB
    __shared__ float vs[BK * KST];   // 9.2 KB
    __shared__ float ps[BQ * PST];   // 8.3 KB

    const int b   = blockIdx.y;
    const int q0  = blockIdx.x * BQ;
    const int tid = threadIdx.x;
    const int qi  = tid >> 3;   // query within tile, 0..31
    const int sub = tid & 7;    // sub-lane within query group, 0..7

    const float* qb = g_q + ((size_t)b * SS + q0) * DD;
    const float* kb = g_k + (size_t)b * SS * DD;
    const float* vb = g_v + (size_t)b * SS * DD;

    // Load Q tile: 32 rows x 8 float4 = 256 float4, one per thread.
    {
        const int row = tid >> 3, c4 = tid & 7;
        const float4 v4 = *(const float4*)(qb + row * DD + c4 * 4);
        *(float4*)&qs[row * KST + c4 * 4] = v4;
    }

    float m = -CUDART_INF_F;
    float l = 0.f;
    float acc0 = 0.f, acc1 = 0.f, acc2 = 0.f, acc3 = 0.f;

    for (int kc = 0; kc < SS; kc += BK) {
        __syncthreads();  // prev PV reads of vs/ps complete; also covers qs store on iter 0

        // Load K/V chunk (64x32 fp32 each): 512 float4 per array / 256 threads.
#pragma unroll
        for (int i = 0; i < 2; i++) {
            const int idx = tid + i * 256;
            const int row = idx >> 3, c4 = idx & 7;
            *(float4*)&ks[row * KST + c4 * 4] = *(const float4*)(kb + (kc + row) * DD + c4 * 4);
            *(float4*)&vs[row * KST + c4 * 4] = *(const float4*)(vb + (kc + row) * DD + c4 * 4);
        }
        __syncthreads();

        // Scores: each thread handles 8 keys (j = sub + 8t).
        float sc[8] = {0.f, 0.f, 0.f, 0.f, 0.f, 0.f, 0.f, 0.f};
#pragma unroll
        for (int e4 = 0; e4 < 8; e4++) {
            const float4 qv = *(const float4*)&qs[qi * KST + e4 * 4];
#pragma unroll
            for (int t = 0; t < 8; t++) {
                const float4 kv = *(const float4*)&ks[(sub + 8 * t) * KST + e4 * 4];
                sc[t] += qv.x * kv.x + qv.y * kv.y;
                sc[t] += qv.z * kv.z + qv.w * kv.w;
            }
        }

        // Chunk max, reduced over the 8-thread query group.
        float cmax = sc[0];
#pragma unroll
        for (int t = 1; t < 8; t++) cmax = fmaxf(cmax, sc[t]);
#pragma unroll
        for (int off = 1; off < 8; off <<= 1)
            cmax = fmaxf(cmax, __shfl_xor_sync(0xffffffffu, cmax, off, 8));

        const float mnew = fmaxf(m, cmax);
        const float corr = __expf(m - mnew);   // exp(-inf)=0 handles first chunk

        float psum = 0.f;
#pragma unroll
        for (int t = 0; t < 8; t++) {
            const float p = __expf(sc[t] - mnew);
            ps[qi * PST + sub + 8 * t] = p;
            psum += p;
        }
#pragma unroll
        for (int off = 1; off < 8; off <<= 1)
            psum += __shfl_xor_sync(0xffffffffu, psum, off, 8);

        l = l * corr + psum;
        m = mnew;
        acc0 *= corr; acc1 *= corr; acc2 *= corr; acc3 *= corr;

        __syncthreads();  // ps visible to whole query group

        // PV: thread owns dims [sub*4, sub*4+4), iterates all 64 keys of chunk.
#pragma unroll 4
        for (int j = 0; j < BK; j++) {
            const float p = ps[qi * PST + j];                       // broadcast
            const float4 vv = *(const float4*)&vs[j * KST + sub * 4];
            acc0 += p * vv.x;
            acc1 += p * vv.y;
            acc2 += p * vv.z;
            acc3 += p * vv.w;
        }
    }

    // Post-softmax scaling (as in reference): out = scaling * softmax @ V
    const float scaling = 0.17677669529663687f;  // 32^-0.5
    const float inv = scaling / l;
    float4 o;
    o.x = acc0 * inv; o.y = acc1 * inv; o.z = acc2 * inv; o.w = acc3 * inv;
    *(float4*)(out + ((size_t)b * SS + q0 + qi) * DD + sub * 4) = o;
}

// ---------------------------------------------------------------------------
extern "C" void kernel_launch(void* const* d_in, const int* in_sizes, int n_in,
                              void* d_out, int out_size)
{
    const float* x  = (const float*)d_in[0];
    const float* Wq = (const float*)d_in[1];
    const float* Wk = (const float*)d_in[2];
    const float* Wv = (const float*)d_in[3];
    float* out = (float*)d_out;

    proj_kernel<<<(BB * SS) / 32, 256>>>(x, Wq, Wk, Wv);

    dim3 grid(SS / BQ, BB);
    attn_kernel<<<grid, 256>>>(out);
}

// round 2
// speedup vs baseline: 1.4867x; 1.4867x over previous
#include <cuda_runtime.h>
#include <math_constants.h>

// Problem constants
#define BB 4
#define SS 4096
#define EE 256
#define DD 32

// Scratch for projected Q/K/V: [B, S, D] fp32 each (2 MB each; static)
__device__ float g_q[BB * SS * DD];
__device__ float g_k[BB * SS * DD];
__device__ float g_v[BB * SS * DD];

// ---------------------------------------------------------------------------
// Projection kernel: q/k/v = x @ W{q,k,v}.  One block = 32 rows of x.
// ---------------------------------------------------------------------------
__global__ __launch_bounds__(256, 1) void proj_kernel(
    const float* __restrict__ x,
    const float* __restrict__ Wq,
    const float* __restrict__ Wk,
    const float* __restrict__ Wv)
{
    __shared__ float xs[32 * EE];  // 32 KB
    const int row0 = blockIdx.x * 32;
    const int tid = threadIdx.x;

    const float4* xg = (const float4*)(x + (size_t)row0 * EE);
    float4* xs4 = (float4*)xs;
#pragma unroll
    for (int i = 0; i < 8; i++) xs4[tid + i * 256] = xg[tid + i * 256];
    __syncthreads();

    const int col = tid & 31;
    const int rg  = tid >> 5;

    float aq[4] = {0.f, 0.f, 0.f, 0.f};
    float ak[4] = {0.f, 0.f, 0.f, 0.f};
    float av[4] = {0.f, 0.f, 0.f, 0.f};

#pragma unroll 4
    for (int e = 0; e < EE; e++) {
        const float wq = __ldg(&Wq[e * DD + col]);
        const float wk = __ldg(&Wk[e * DD + col]);
        const float wv = __ldg(&Wv[e * DD + col]);
#pragma unroll
        for (int rr = 0; rr < 4; rr++) {
            const float xv = xs[(rg * 4 + rr) * EE + e];
            aq[rr] += xv * wq;
            ak[rr] += xv * wk;
            av[rr] += xv * wv;
        }
    }

#pragma unroll
    for (int rr = 0; rr < 4; rr++) {
        const int r = row0 + rg * 4 + rr;
        g_q[r * DD + col] = aq[rr];
        g_k[r * DD + col] = ak[rr];
        g_v[r * DD + col] = av[rr];
    }
}

// ---------------------------------------------------------------------------
// Flash attention, register-blocked.
// Block: 256 threads. BQ=64 queries, BK=64 keys per chunk.
// QK phase: thread (qg,kg) in 16x16 grid owns 4q x 4k register tile,
//           queries qg+16i, keys kg+16j (interleaved -> conflict-free LDS).
// PV phase: thread (qg2,dg) in 32x8 grid owns 2q x 4d tile.
// Softmax state (m,l) lives in QK mapping; per-chunk corr handed to PV via cs[].
// ---------------------------------------------------------------------------
#define BQ 64
#define BK 64
#define KST 36   // q/k/v smem row stride (floats): float4-aligned, conflict-free
#define PST 80   // p smem row stride: STS conflict-free for (80*qg+kg) pattern

__global__ __launch_bounds__(256, 2) void attn_kernel(float* __restrict__ out)
{
    __shared__ float qs[BQ * KST];   // 9.0 KB
    __shared__ float ks[BK * KST];   // 9.0 KB
    __shared__ float vs[BK * KST];   // 9.0 KB
    __shared__ float ps[BQ * PST];   // 20.0 KB
    __shared__ float cs[BQ];         // per-query correction factor this chunk
    __shared__ float ls[BQ];         // final softmax denominators

    const int b   = blockIdx.y;
    const int q0  = blockIdx.x * BQ;
    const int tid = threadIdx.x;
    const int qg  = tid >> 4;   // 0..15  (QK mapping)
    const int kg  = tid & 15;   // 0..15
    const int qg2 = tid >> 3;   // 0..31  (PV mapping)
    const int dg  = tid & 7;    // 0..7

    const float* qb = g_q + ((size_t)b * SS + q0) * DD;
    const float* kb = g_k + (size_t)b * SS * DD;
    const float* vb = g_v + (size_t)b * SS * DD;

    // Load Q tile: 64 rows x 8 float4 = 512 float4.
#pragma unroll
    for (int i = 0; i < 2; i++) {
        const int idx = tid + i * 256;
        const int row = idx >> 3, c4 = idx & 7;
        *(float4*)&qs[row * KST + c4 * 4] = *(const float4*)(qb + row * DD + c4 * 4);
    }

    float m[4], l[4];
#pragma unroll
    for (int i = 0; i < 4; i++) { m[i] = -CUDART_INF_F; l[i] = 0.f; }
    float a0x = 0.f, a0y = 0.f, a0z = 0.f, a0w = 0.f;   // acc for query qg2
    float a1x = 0.f, a1y = 0.f, a1z = 0.f, a1w = 0.f;   // acc for query qg2+32

    for (int kc = 0; kc < SS; kc += BK) {
        __syncthreads();   // prior PV reads of vs/ps/cs done (also covers qs on iter 0)

        // Load K/V chunk: 512 float4 each.
#pragma unroll
        for (int i = 0; i < 2; i++) {
            const int idx = tid + i * 256;
            const int row = idx >> 3, c4 = idx & 7;
            *(float4*)&ks[row * KST + c4 * 4] = *(const float4*)(kb + (kc + row) * DD + c4 * 4);
            *(float4*)&vs[row * KST + c4 * 4] = *(const float4*)(vb + (kc + row) * DD + c4 * 4);
        }
        __syncthreads();

        // ---- QK: 4x4 register tile ----
        float s[4][4];
#pragma unroll
        for (int i = 0; i < 4; i++)
#pragma unroll
            for (int j = 0; j < 4; j++) s[i][j] = 0.f;

#pragma unroll
        for (int e4 = 0; e4 < 8; e4++) {
            float4 qv[4], kv[4];
#pragma unroll
            for (int i = 0; i < 4; i++) qv[i] = *(const float4*)&qs[(qg + 16 * i) * KST + e4 * 4];
#pragma unroll
            for (int j = 0; j < 4; j++) kv[j] = *(const float4*)&ks[(kg + 16 * j) * KST + e4 * 4];
#pragma unroll
            for (int i = 0; i < 4; i++)
#pragma unroll
                for (int j = 0; j < 4; j++) {
                    s[i][j] += qv[i].x * kv[j].x + qv[i].y * kv[j].y;
                    s[i][j] += qv[i].z * kv[j].z + qv[i].w * kv[j].w;
                }
        }

        // ---- online softmax over this chunk (per query row i) ----
#pragma unroll
        for (int i = 0; i < 4; i++) {
            float rmax = fmaxf(fmaxf(s[i][0], s[i][1]), fmaxf(s[i][2], s[i][3]));
#pragma unroll
            for (int off = 1; off < 16; off <<= 1)
                rmax = fmaxf(rmax, __shfl_xor_sync(0xffffffffu, rmax, off, 16));

            const float mnew = fmaxf(m[i], rmax);
            const float corr = __expf(m[i] - mnew);   // exp(-inf)=0 on first chunk
            float psum = 0.f;
#pragma unroll
            for (int j = 0; j < 4; j++) {
                const float p = __expf(s[i][j] - mnew);
                ps[(qg + 16 * i) * PST + kg + 16 * j] = p;
                psum += p;
            }
#pragma unroll
            for (int off = 1; off < 16; off <<= 1)
                psum += __shfl_xor_sync(0xffffffffu, psum, off, 16);

            l[i] = l[i] * corr + psum;
            m[i] = mnew;
            if (kg == 0) cs[qg + 16 * i] = corr;
        }
        __syncthreads();   // ps/cs ready for PV mapping

        // ---- PV: 2q x 4d register tile ----
        const float c0 = cs[qg2];
        const float c1 = cs[qg2 + 32];
        a0x *= c0; a0y *= c0; a0z *= c0; a0w *= c0;
        a1x *= c1; a1y *= c1; a1z *= c1; a1w *= c1;

        const float* p0r = &ps[qg2 * PST];
        const float* p1r = &ps[(qg2 + 32) * PST];
#pragma unroll 8
        for (int j = 0; j < BK; j++) {
            const float p0 = p0r[j];
            const float p1 = p1r[j];
            const float4 vv = *(const float4*)&vs[j * KST + dg * 4];
            a0x += p0 * vv.x; a0y += p0 * vv.y; a0z += p0 * vv.z; a0w += p0 * vv.w;
            a1x += p1 * vv.x; a1y += p1 * vv.y; a1z += p1 * vv.z; a1w += p1 * vv.w;
        }
    }

    // Hand softmax denominators from QK mapping to PV mapping.
    if (kg == 0) {
#pragma unroll
        for (int i = 0; i < 4; i++) ls[qg + 16 * i] = l[i];
    }
    __syncthreads();

    const float scaling = 0.17677669529663687f;  // 32^-0.5 (post-softmax, per reference)
    const float inv0 = scaling / ls[qg2];
    const float inv1 = scaling / ls[qg2 + 32];

    float4 o0, o1;
    o0.x = a0x * inv0; o0.y = a0y * inv0; o0.z = a0z * inv0; o0.w = a0w * inv0;
    o1.x = a1x * inv1; o1.y = a1y * inv1; o1.z = a1z * inv1; o1.w = a1w * inv1;
    *(float4*)(out + ((size_t)b * SS + q0 + qg2) * DD + dg * 4) = o0;
    *(float4*)(out + ((size_t)b * SS + q0 + qg2 + 32) * DD + dg * 4) = o1;
}

// ---------------------------------------------------------------------------
extern "C" void kernel_launch(void* const* d_in, const int* in_sizes, int n_in,
                              void* d_out, int out_size)
{
    const float* x  = (const float*)d_in[0];
    const float* Wq = (const float*)d_in[1];
    const float* Wk = (const float*)d_in[2];
    const float* Wv = (const float*)d_in[3];
    float* out = (float*)d_out;

    proj_kernel<<<(BB * SS) / 32, 256>>>(x, Wq, Wk, Wv);

    dim3 grid(SS / BQ, BB);
    attn_kernel<<<grid, 256>>>(out);
}

// round 3
// speedup vs baseline: 1.9788x; 1.3310x over previous
#include <cuda_runtime.h>
#include <math_constants.h>

// Problem constants
#define BB 4
#define SS 4096
#define EE 256
#define DD 32

// Scratch for projected Q/K/V: [B, S, D] fp32 each (2 MB each; static)
__device__ float g_q[BB * SS * DD];
__device__ float g_k[BB * SS * DD];
__device__ float g_v[BB * SS * DD];

// ---------------------------------------------------------------------------
// Projection kernel: q/k/v = x @ W{q,k,v}.  One block = 32 rows of x.
// ---------------------------------------------------------------------------
__global__ __launch_bounds__(256, 1) void proj_kernel(
    const float* __restrict__ x,
    const float* __restrict__ Wq,
    const float* __restrict__ Wk,
    const float* __restrict__ Wv)
{
    __shared__ float xs[32 * EE];  // 32 KB
    const int row0 = blockIdx.x * 32;
    const int tid = threadIdx.x;

    const float4* xg = (const float4*)(x + (size_t)row0 * EE);
    float4* xs4 = (float4*)xs;
#pragma unroll
    for (int i = 0; i < 8; i++) xs4[tid + i * 256] = xg[tid + i * 256];
    __syncthreads();

    const int col = tid & 31;
    const int rg  = tid >> 5;

    float aq[4] = {0.f, 0.f, 0.f, 0.f};
    float ak[4] = {0.f, 0.f, 0.f, 0.f};
    float av[4] = {0.f, 0.f, 0.f, 0.f};

#pragma unroll 4
    for (int e = 0; e < EE; e++) {
        const float wq = __ldg(&Wq[e * DD + col]);
        const float wk = __ldg(&Wk[e * DD + col]);
        const float wv = __ldg(&Wv[e * DD + col]);
#pragma unroll
        for (int rr = 0; rr < 4; rr++) {
            const float xv = xs[(rg * 4 + rr) * EE + e];
            aq[rr] += xv * wq;
            ak[rr] += xv * wk;
            av[rr] += xv * wv;
        }
    }

#pragma unroll
    for (int rr = 0; rr < 4; rr++) {
        const int r = row0 + rg * 4 + rr;
        g_q[r * DD + col] = aq[rr];
        g_k[r * DD + col] = ak[rr];
        g_v[r * DD + col] = av[rr];
    }
}

// ---------------------------------------------------------------------------
// Flash attention, single mapping, P entirely in registers.
// Block: 256 threads = 16x16 grid (qg, kg).
//   Thread owns queries qg+16i (i<4), keys kg+16j (j<4) of each 64-key chunk.
//   QK scores s[4][4] -> softmax (16-lane shfl reduces) -> p kept in regs.
//   PV accumulated into PARTIAL acc[4][32] (this thread's 4 keys only);
//   reduced over the 16 kg-lanes by butterfly shuffles once at the end.
// Online-softmax rescale of acc guarded by (mnew > m): taken only on record
// maxima (~5 of 64 chunks), so the 128-reg rescale is amortized away.
// ---------------------------------------------------------------------------
#define BQ 64
#define BK 64
#define KST 36   // smem row stride (floats): float4-aligned

__global__ __launch_bounds__(256, 1) void attn_kernel(float* __restrict__ out)
{
    __shared__ float qs[BQ * KST];   // 9.0 KB
    __shared__ float ks[BK * KST];   // 9.0 KB
    __shared__ float vs[BK * KST];   // 9.0 KB

    const int b   = blockIdx.y;
    const int q0  = blockIdx.x * BQ;
    const int tid = threadIdx.x;
    const int qg  = tid >> 4;   // 0..15
    const int kg  = tid & 15;   // 0..15

    const float* qb = g_q + ((size_t)b * SS + q0) * DD;
    const float* kb = g_k + (size_t)b * SS * DD;
    const float* vb = g_v + (size_t)b * SS * DD;

    // Per-thread cooperative-load coordinates (64 rows x 8 float4 per tile).
    const int lrow0 = tid >> 3,           lc0 = tid & 7;          // idx = tid
    const int lrow1 = (tid + 256) >> 3,   lc1 = tid & 7;          // idx = tid+256

    // Load Q tile.
    *(float4*)&qs[lrow0 * KST + lc0 * 4] = *(const float4*)(qb + lrow0 * DD + lc0 * 4);
    *(float4*)&qs[lrow1 * KST + lc1 * 4] = *(const float4*)(qb + lrow1 * DD + lc1 * 4);

    // Prefetch chunk 0 of K/V into registers.
    float4 kr0 = *(const float4*)(kb + lrow0 * DD + lc0 * 4);
    float4 kr1 = *(const float4*)(kb + lrow1 * DD + lc1 * 4);
    float4 vr0 = *(const float4*)(vb + lrow0 * DD + lc0 * 4);
    float4 vr1 = *(const float4*)(vb + lrow1 * DD + lc1 * 4);

    float4 acc[4][8];
#pragma unroll
    for (int i = 0; i < 4; i++)
#pragma unroll
        for (int c = 0; c < 8; c++) acc[i][c] = make_float4(0.f, 0.f, 0.f, 0.f);

    float m[4], l[4];
#pragma unroll
    for (int i = 0; i < 4; i++) { m[i] = -CUDART_INF_F; l[i] = 0.f; }

    for (int kc = 0; kc < SS; kc += BK) {
        __syncthreads();   // previous chunk's smem reads complete

        // Commit prefetched K/V to smem.
        *(float4*)&ks[lrow0 * KST + lc0 * 4] = kr0;
        *(float4*)&ks[lrow1 * KST + lc1 * 4] = kr1;
        *(float4*)&vs[lrow0 * KST + lc0 * 4] = vr0;
        *(float4*)&vs[lrow1 * KST + lc1 * 4] = vr1;
        __syncthreads();

        // Prefetch next chunk (LDG latency hidden behind compute below).
        if (kc + BK < SS) {
            const float* kn = kb + (size_t)(kc + BK) * DD;
            const float* vn = vb + (size_t)(kc + BK) * DD;
            kr0 = *(const float4*)(kn + lrow0 * DD + lc0 * 4);
            kr1 = *(const float4*)(kn + lrow1 * DD + lc1 * 4);
            vr0 = *(const float4*)(vn + lrow0 * DD + lc0 * 4);
            vr1 = *(const float4*)(vn + lrow1 * DD + lc1 * 4);
        }

        // ---- QK: 4x4 register tile ----
        float s[4][4];
#pragma unroll
        for (int i = 0; i < 4; i++)
#pragma unroll
            for (int j = 0; j < 4; j++) s[i][j] = 0.f;

#pragma unroll
        for (int e4 = 0; e4 < 8; e4++) {
            float4 qv[4], kv[4];
#pragma unroll
            for (int i = 0; i < 4; i++) qv[i] = *(const float4*)&qs[(qg + 16 * i) * KST + e4 * 4];
#pragma unroll
            for (int j = 0; j < 4; j++) kv[j] = *(const float4*)&ks[(kg + 16 * j) * KST + e4 * 4];
#pragma unroll
            for (int i = 0; i < 4; i++)
#pragma unroll
                for (int j = 0; j < 4; j++) {
                    s[i][j] += qv[i].x * kv[j].x + qv[i].y * kv[j].y;
                    s[i][j] += qv[i].z * kv[j].z + qv[i].w * kv[j].w;
                }
        }

        // ---- online softmax; p overwrites s ----
#pragma unroll
        for (int i = 0; i < 4; i++) {
            float rmax = fmaxf(fmaxf(s[i][0], s[i][1]), fmaxf(s[i][2], s[i][3]));
#pragma unroll
            for (int off = 1; off < 16; off <<= 1)
                rmax = fmaxf(rmax, __shfl_xor_sync(0xffffffffu, rmax, off, 16));

            if (rmax > m[i]) {                      // record max: rescale (rare)
                const float corr = __expf(m[i] - rmax);   // exp(-inf)=0 on chunk 0
                l[i] *= corr;
#pragma unroll
                for (int c = 0; c < 8; c++) {
                    acc[i][c].x *= corr; acc[i][c].y *= corr;
                    acc[i][c].z *= corr; acc[i][c].w *= corr;
                }
                m[i] = rmax;
            }

            float psum = 0.f;
#pragma unroll
            for (int j = 0; j < 4; j++) {
                const float p = __expf(s[i][j] - m[i]);
                s[i][j] = p;
                psum += p;
            }
#pragma unroll
            for (int off = 1; off < 16; off <<= 1)
                psum += __shfl_xor_sync(0xffffffffu, psum, off, 16);
            l[i] += psum;
        }

        // ---- PV: partial accumulation over this thread's 4 keys ----
#pragma unroll
        for (int c = 0; c < 8; c++) {
            float4 vv[4];
#pragma unroll
            for (int j = 0; j < 4; j++) vv[j] = *(const float4*)&vs[(kg + 16 * j) * KST + c * 4];
#pragma unroll
            for (int i = 0; i < 4; i++)
#pragma unroll
                for (int j = 0; j < 4; j++) {
                    acc[i][c].x += s[i][j] * vv[j].x;
                    acc[i][c].y += s[i][j] * vv[j].y;
                    acc[i][c].z += s[i][j] * vv[j].z;
                    acc[i][c].w += s[i][j] * vv[j].w;
                }
        }
    }

    // ---- butterfly-reduce partial acc over the 16 kg-lanes (intra-warp) ----
#pragma unroll
    for (int i = 0; i < 4; i++)
#pragma unroll
        for (int c = 0; c < 8; c++) {
#pragma unroll
            for (int off = 1; off < 16; off <<= 1) {
                acc[i][c].x += __shfl_xor_sync(0xffffffffu, acc[i][c].x, off, 16);
                acc[i][c].y += __shfl_xor_sync(0xffffffffu, acc[i][c].y, off, 16);
                acc[i][c].z += __shfl_xor_sync(0xffffffffu, acc[i][c].z, off, 16);
                acc[i][c].w += __shfl_xor_sync(0xffffffffu, acc[i][c].w, off, 16);
            }
        }

    // ---- write: lane kg==c writes float4 column c (static unrolled select) ----
    const float scaling = 0.17677669529663687f;  // 32^-0.5 (post-softmax, per reference)
#pragma unroll
    for (int i = 0; i < 4; i++) {
        const float inv = scaling / l[i];
        float* orow = out + ((size_t)b * SS + q0 + qg + 16 * i) * DD;
#pragma unroll
        for (int c = 0; c < 8; c++) {
            if (kg == c) {
                float4 o;
                o.x = acc[i][c].x * inv; o.y = acc[i][c].y * inv;
                o.z = acc[i][c].z * inv; o.w = acc[i][c].w * inv;
                *(float4*)(orow + c * 4) = o;
            }
        }
    }
}

// ---------------------------------------------------------------------------
extern "C" void kernel_launch(void* const* d_in, const int* in_sizes, int n_in,
                              void* d_out, int out_size)
{
    const float* x  = (const float*)d_in[0];
    const float* Wq = (const float*)d_in[1];
    const float* Wk = (const float*)d_in[2];
    const float* Wv = (const float*)d_in[3];
    float* out = (float*)d_out;

    proj_kernel<<<(BB * SS) / 32, 256>>>(x, Wq, Wk, Wv);

    dim3 grid(SS / BQ, BB);
    attn_kernel<<<grid, 256>>>(out);
}

// round 4
// speedup vs baseline: 2.3305x; 1.1778x over previous
#include <cuda_runtime.h>
#include <math_constants.h>

// Problem constants
#define BB 4
#define SS 4096
#define EE 256
#define DD 32

typedef unsigned long long ull;

// ---- packed f32x2 helpers (sm_103a FFMA2 path; PTX-only per SASS_QUICKREF) ----
__device__ __forceinline__ ull ffma2(ull a, ull b, ull c) {
    ull d;
    asm("fma.rn.f32x2 %0, %1, %2, %3;" : "=l"(d) : "l"(a), "l"(b), "l"(c));
    return d;
}
__device__ __forceinline__ ull fmul2(ull a, ull b) {
    ull d;
    asm("mul.rn.f32x2 %0, %1, %2;" : "=l"(d) : "l"(a), "l"(b));
    return d;
}
__device__ __forceinline__ ull pack2(float x, float y) {
    ull r; asm("mov.b64 %0, {%1, %2};" : "=l"(r) : "f"(x), "f"(y)); return r;
}
__device__ __forceinline__ float2 unpack2(ull u) {
    float2 v; asm("mov.b64 {%0, %1}, %2;" : "=f"(v.x), "=f"(v.y) : "l"(u)); return v;
}

// Scratch for projected Q/K/V: [B, S, D] fp32 each (static)
__device__ float g_q[BB * SS * DD];
__device__ float g_k[BB * SS * DD];
__device__ float g_v[BB * SS * DD];

// ---------------------------------------------------------------------------
// Projection kernel, f32x2-packed over e-pairs. One block = 32 rows of x.
// ---------------------------------------------------------------------------
__global__ __launch_bounds__(256, 1) void proj_kernel(
    const float* __restrict__ x,
    const float* __restrict__ Wq,
    const float* __restrict__ Wk,
    const float* __restrict__ Wv)
{
    __shared__ float xs[32 * EE];  // 32 KB
    const int row0 = blockIdx.x * 32;
    const int tid = threadIdx.x;

    const float4* xg = (const float4*)(x + (size_t)row0 * EE);
    float4* xs4 = (float4*)xs;
#pragma unroll
    for (int i = 0; i < 8; i++) xs4[tid + i * 256] = xg[tid + i * 256];
    __syncthreads();

    const int col = tid & 31;
    const int rg  = tid >> 5;

    ull aq2[4], ak2[4], av2[4];
#pragma unroll
    for (int rr = 0; rr < 4; rr++) { aq2[rr] = 0; ak2[rr] = 0; av2[rr] = 0; }

#pragma unroll 2
    for (int e = 0; e < EE; e += 2) {
        const ull wq2 = pack2(__ldg(&Wq[e * DD + col]), __ldg(&Wq[(e + 1) * DD + col]));
        const ull wk2 = pack2(__ldg(&Wk[e * DD + col]), __ldg(&Wk[(e + 1) * DD + col]));
        const ull wv2 = pack2(__ldg(&Wv[e * DD + col]), __ldg(&Wv[(e + 1) * DD + col]));
#pragma unroll
        for (int rr = 0; rr < 4; rr++) {
            const ull xv2 = *(const ull*)&xs[(rg * 4 + rr) * EE + e];  // 8B-aligned (e even)
            aq2[rr] = ffma2(xv2, wq2, aq2[rr]);
            ak2[rr] = ffma2(xv2, wk2, ak2[rr]);
            av2[rr] = ffma2(xv2, wv2, av2[rr]);
        }
    }

#pragma unroll
    for (int rr = 0; rr < 4; rr++) {
        const int r = row0 + rg * 4 + rr;
        const float2 q2 = unpack2(aq2[rr]);
        const float2 k2 = unpack2(ak2[rr]);
        const float2 v2 = unpack2(av2[rr]);
        g_q[r * DD + col] = q2.x + q2.y;
        g_k[r * DD + col] = k2.x + k2.y;
        g_v[r * DD + col] = v2.x + v2.y;
    }
}

// ---------------------------------------------------------------------------
// Flash attention, P in registers, f32x2-packed FMA throughout.
// Block: 256 threads = 16x16 (qg, kg); thread owns 4 queries x 4 keys,
// partial PV acc over its keys (reduced by 16-lane butterflies at the end).
// ---------------------------------------------------------------------------
#define BQ 64
#define BK 64
#define KST 36   // smem row stride (floats): float4-aligned, conflict-free

__global__ __launch_bounds__(256, 1) void attn_kernel(float* __restrict__ out)
{
    __shared__ float qs[BQ * KST];
    __shared__ float ks[BK * KST];
    __shared__ float vs[BK * KST];

    const int b   = blockIdx.y;
    const int q0  = blockIdx.x * BQ;
    const int tid = threadIdx.x;
    const int qg  = tid >> 4;   // 0..15
    const int kg  = tid & 15;   // 0..15

    const float* qb = g_q + ((size_t)b * SS + q0) * DD;
    const float* kb = g_k + (size_t)b * SS * DD;
    const float* vb = g_v + (size_t)b * SS * DD;

    const int lrow0 = tid >> 3,         lc0 = tid & 7;
    const int lrow1 = (tid + 256) >> 3, lc1 = tid & 7;

    // Load Q tile (64 x 32 fp32).
    *(float4*)&qs[lrow0 * KST + lc0 * 4] = *(const float4*)(qb + lrow0 * DD + lc0 * 4);
    *(float4*)&qs[lrow1 * KST + lc1 * 4] = *(const float4*)(qb + lrow1 * DD + lc1 * 4);

    // Prefetch chunk 0 of K/V.
    float4 kr0 = *(const float4*)(kb + lrow0 * DD + lc0 * 4);
    float4 kr1 = *(const float4*)(kb + lrow1 * DD + lc1 * 4);
    float4 vr0 = *(const float4*)(vb + lrow0 * DD + lc0 * 4);
    float4 vr1 = *(const float4*)(vb + lrow1 * DD + lc1 * 4);

    ull acc2[4][16];   // 4 queries x 32 dims as 16 f32x2 pairs (128 regs)
#pragma unroll
    for (int i = 0; i < 4; i++)
#pragma unroll
        for (int c = 0; c < 16; c++) acc2[i][c] = 0;

    float m[4], l[4];
#pragma unroll
    for (int i = 0; i < 4; i++) { m[i] = -CUDART_INF_F; l[i] = 0.f; }

    for (int kc = 0; kc < SS; kc += BK) {
        __syncthreads();

        *(float4*)&ks[lrow0 * KST + lc0 * 4] = kr0;
        *(float4*)&ks[lrow1 * KST + lc1 * 4] = kr1;
        *(float4*)&vs[lrow0 * KST + lc0 * 4] = vr0;
        *(float4*)&vs[lrow1 * KST + lc1 * 4] = vr1;
        __syncthreads();

        if (kc + BK < SS) {
            const float* kn = kb + (size_t)(kc + BK) * DD;
            const float* vn = vb + (size_t)(kc + BK) * DD;
            kr0 = *(const float4*)(kn + lrow0 * DD + lc0 * 4);
            kr1 = *(const float4*)(kn + lrow1 * DD + lc1 * 4);
            vr0 = *(const float4*)(vn + lrow0 * DD + lc0 * 4);
            vr1 = *(const float4*)(vn + lrow1 * DD + lc1 * 4);
        }

        // ---- QK: 4x4 tile, packed partial dots ----
        ull sp[4][4];
#pragma unroll
        for (int i = 0; i < 4; i++)
#pragma unroll
            for (int j = 0; j < 4; j++) sp[i][j] = 0;

#pragma unroll
        for (int e4 = 0; e4 < 8; e4++) {
            ulonglong2 qv[4], kv[4];
#pragma unroll
            for (int i = 0; i < 4; i++)
                qv[i] = *(const ulonglong2*)&qs[(qg + 16 * i) * KST + e4 * 4];
#pragma unroll
            for (int j = 0; j < 4; j++)
                kv[j] = *(const ulonglong2*)&ks[(kg + 16 * j) * KST + e4 * 4];
#pragma unroll
            for (int i = 0; i < 4; i++)
#pragma unroll
                for (int j = 0; j < 4; j++) {
                    sp[i][j] = ffma2(qv[i].x, kv[j].x, sp[i][j]);
                    sp[i][j] = ffma2(qv[i].y, kv[j].y, sp[i][j]);
                }
        }

        // ---- online softmax; sp becomes packed (p,p) ----
#pragma unroll
        for (int i = 0; i < 4; i++) {
            float s[4];
#pragma unroll
            for (int j = 0; j < 4; j++) {
                const float2 t = unpack2(sp[i][j]);
                s[j] = t.x + t.y;
            }
            float rmax = fmaxf(fmaxf(s[0], s[1]), fmaxf(s[2], s[3]));
#pragma unroll
            for (int off = 1; off < 16; off <<= 1)
                rmax = fmaxf(rmax, __shfl_xor_sync(0xffffffffu, rmax, off, 16));

            if (rmax > m[i]) {               // record max: rescale (rare)
                const float corr = __expf(m[i] - rmax);
                l[i] *= corr;
                const ull c2 = pack2(corr, corr);
#pragma unroll
                for (int c = 0; c < 16; c++) acc2[i][c] = fmul2(acc2[i][c], c2);
                m[i] = rmax;
            }

            float psum = 0.f;
#pragma unroll
            for (int j = 0; j < 4; j++) {
                const float p = __expf(s[j] - m[i]);
                sp[i][j] = pack2(p, p);
                psum += p;
            }
#pragma unroll
            for (int off = 1; off < 16; off <<= 1)
                psum += __shfl_xor_sync(0xffffffffu, psum, off, 16);
            l[i] += psum;
        }

        // ---- PV: packed partial accumulation over this thread's 4 keys ----
#pragma unroll
        for (int c = 0; c < 8; c++) {
            ulonglong2 vv[4];
#pragma unroll
            for (int j = 0; j < 4; j++)
                vv[j] = *(const ulonglong2*)&vs[(kg + 16 * j) * KST + c * 4];
#pragma unroll
            for (int i = 0; i < 4; i++)
#pragma unroll
                for (int j = 0; j < 4; j++) {
                    acc2[i][2 * c]     = ffma2(sp[i][j], vv[j].x, acc2[i][2 * c]);
                    acc2[i][2 * c + 1] = ffma2(sp[i][j], vv[j].y, acc2[i][2 * c + 1]);
                }
        }
    }

    // ---- butterfly-reduce partials over the 16 kg lanes; write out ----
    const float scaling = 0.17677669529663687f;  // 32^-0.5 (post-softmax, per reference)
#pragma unroll
    for (int i = 0; i < 4; i++) {
        const float inv = scaling / l[i];
        float* orow = out + ((size_t)b * SS + q0 + qg + 16 * i) * DD;
#pragma unroll
        for (int c = 0; c < 8; c++) {
            float2 lo = unpack2(acc2[i][2 * c]);
            float2 hi = unpack2(acc2[i][2 * c + 1]);
#pragma unroll
            for (int off = 1; off < 16; off <<= 1) {
                lo.x += __shfl_xor_sync(0xffffffffu, lo.x, off, 16);
                lo.y += __shfl_xor_sync(0xffffffffu, lo.y, off, 16);
                hi.x += __shfl_xor_sync(0xffffffffu, hi.x, off, 16);
                hi.y += __shfl_xor_sync(0xffffffffu, hi.y, off, 16);
            }
            if (kg == c) {
                float4 o;
                o.x = lo.x * inv; o.y = lo.y * inv;
                o.z = hi.x * inv; o.w = hi.y * inv;
                *(float4*)(orow + c * 4) = o;
            }
        }
    }
}

// ---------------------------------------------------------------------------
extern "C" void kernel_launch(void* const* d_in, const int* in_sizes, int n_in,
                              void* d_out, int out_size)
{
    const float* x  = (const float*)d_in[0];
    const float* Wq = (const float*)d_in[1];
    const float* Wk = (const float*)d_in[2];
    const float* Wv = (const float*)d_in[3];
    float* out = (float*)d_out;

    proj_kernel<<<(BB * SS) / 32, 256>>>(x, Wq, Wk, Wv);

    dim3 grid(SS / BQ, BB);
    attn_kernel<<<grid, 256>>>(out);
}